// round 11
// baseline (speedup 1.0000x reference)
#include <cuda_runtime.h>
#include <cuda_fp16.h>
#include <stdint.h>

#define TT 512
#define NB 256
#define HH 256
#define GG 1024

// vcol = jj*4 + gate  (jj = hidden col; gate: 0=i 1=f 2=g 3=o)
__device__ __half   g_xh[(size_t)NB * TT * 256];  // x in fp16 [n][t][d]
__device__ __half   g_hh[2 * NB * HH];            // fp16 hidden, double buffered
__device__ __half   g_wtx[1024 * 256];            // [vcol][k] Wx fp16
__device__ __half   g_wth[1024 * 256];            // [vcol][k] Wh fp16
__device__ float    g_bvc[1024];                  // combined bias per vcol
__device__ unsigned g_bars[8 * 32];

__device__ __forceinline__ void mma16(float d[4], uint32_t a0, uint32_t a1,
                                      uint32_t a2, uint32_t a3, uint32_t b0, uint32_t b1) {
    asm volatile("mma.sync.aligned.m16n8k16.row.col.f32.f16.f16.f32 "
                 "{%0,%1,%2,%3}, {%4,%5,%6,%7}, {%8,%9}, {%0,%1,%2,%3};\n"
                 : "+f"(d[0]), "+f"(d[1]), "+f"(d[2]), "+f"(d[3])
                 : "r"(a0), "r"(a1), "r"(a2), "r"(a3), "r"(b0), "r"(b1));
}
__device__ __forceinline__ float sigm(float x) { return __fdividef(1.f, 1.f + __expf(-x)); }
__device__ __forceinline__ float tanh_acc(float x) { return 1.f - __fdividef(2.f, __expf(2.f * x) + 1.f); }
__device__ __forceinline__ unsigned ld_acq(const unsigned* p) {
    unsigned v; asm volatile("ld.acquire.gpu.global.u32 %0, [%1];" : "=r"(v) : "l"(p)); return v;
}
__device__ __forceinline__ void red_rel(unsigned* p, unsigned v) {
    asm volatile("red.release.gpu.global.add.u32 [%0], %1;" :: "l"(p), "r"(v) : "memory");
}
__device__ __forceinline__ uint32_t smem_u32(const void* p) {
    return (uint32_t)__cvta_generic_to_shared(p);
}
__device__ __forceinline__ void ldsm4(uint32_t& a0, uint32_t& a1, uint32_t& a2,
                                      uint32_t& a3, uint32_t addr) {
    asm volatile("ldmatrix.sync.aligned.m8n8.x4.shared.b16 {%0,%1,%2,%3}, [%4];"
                 : "=r"(a0), "=r"(a1), "=r"(a2), "=r"(a3) : "r"(addr));
}

// ============ Prep kernels ================================================
__global__ void prep_w(const float* __restrict__ xi, const float* __restrict__ xf,
                       const float* __restrict__ xg, const float* __restrict__ xo,
                       const float* __restrict__ hi, const float* __restrict__ hf,
                       const float* __restrict__ hg, const float* __restrict__ ho) {
    int which = blockIdx.x >> 10, vv = blockIdx.x & 1023;
    int jj = vv >> 2, gt = vv & 3, k = threadIdx.x;
    const float* w;
    if (which == 0) w = (gt == 0) ? xi : (gt == 1) ? xf : (gt == 2) ? xg : xo;
    else            w = (gt == 0) ? hi : (gt == 1) ? hf : (gt == 2) ? hg : ho;
    __half* dst = which == 0 ? g_wtx : g_wth;
    dst[((size_t)vv << 8) + k] = __float2half_rn(w[k * 256 + jj]);
}
__global__ void prep_b(const float* __restrict__ b0, const float* __restrict__ b1,
                       const float* __restrict__ b2, const float* __restrict__ b3,
                       const float* __restrict__ b4, const float* __restrict__ b5,
                       const float* __restrict__ b6, const float* __restrict__ b7) {
    int vv = blockIdx.x * 256 + threadIdx.x;
    int jj = vv >> 2, gt = vv & 3;
    const float* bx = (gt == 0) ? b0 : (gt == 1) ? b2 : (gt == 2) ? b4 : b6;
    const float* bh = (gt == 0) ? b1 : (gt == 1) ? b3 : (gt == 2) ? b5 : b7;
    g_bvc[vv] = bx[jj] + bh[jj];
}
__global__ void prep_x(const float* __restrict__ x) {
    size_t i = ((size_t)blockIdx.x * 256 + threadIdx.x);
    float4 v = *(const float4*)(x + i * 4);
    __half2 h0 = __floats2half2_rn(v.x, v.y);
    __half2 h1 = __floats2half2_rn(v.z, v.w);
    uint2 pk; pk.x = *(uint32_t*)&h0; pk.y = *(uint32_t*)&h1;
    *(uint2*)(g_xh + i * 4) = pk;
}

// ================= Fused persistent LSTM, 1 block barrier / step ===========
// 128 CTAs: bn=blk>>4, bj=blk&15. 8 warps: wm=warp&1, wc=warp>>1.
// Warp: 16 rows x 16 vcols. Wx+Wh fragments in registers. h_s/x_s double-
// buffered in dynamic smem. Per step: x-mma | stage x(t+1) | per-warp poll |
// per-warp stage h | ONE syncthreads | h-mma | cell | shfl-gather STG |
// per-warp release.
#define HSH 264
#define REC_SMEM (4 * 32 * HSH * 2)

__global__ void __launch_bounds__(256, 1) lstm_rec_kernel(
    float* __restrict__ out, int out_n)
{
    extern __shared__ __align__(16) __half sm[];
    __half* h_b[2] = { sm,               sm + 32 * HSH };
    __half* x_b[2] = { sm + 2 * 32 * HSH, sm + 3 * 32 * HSH };

    const int tid = threadIdx.x, lane = tid & 31, warp = tid >> 5;
    const int wm = warp & 1, wc = warp >> 1;
    const int bn = blockIdx.x >> 4, bj = blockIdx.x & 15;
    const int nBase = bn * 32, j0 = bj * 16;
    const int u = lane >> 2, r = lane & 3;
    const int rA = wm * 16 + u;

    unsigned* bar = &g_bars[bn * 32];

    // ---- persistent B fragments: Wh and Wx ----
    uint32_t hb0[16][2], hb1[16][2], xb0[16][2], xb1[16][2];
    #pragma unroll
    for (int nt = 0; nt < 2; nt++) {
        const size_t vrow = (size_t)(bj * 64 + wc * 16 + nt * 8 + u) * 256;
        const __half* wph = g_wth + vrow;
        const __half* wpx = g_wtx + vrow;
        #pragma unroll
        for (int kc = 0; kc < 16; kc++) {
            hb0[kc][nt] = *(const uint32_t*)(wph + kc * 16 + 2 * r);
            hb1[kc][nt] = *(const uint32_t*)(wph + kc * 16 + 2 * r + 8);
            xb0[kc][nt] = *(const uint32_t*)(wpx + kc * 16 + 2 * r);
            xb1[kc][nt] = *(const uint32_t*)(wpx + kc * 16 + 2 * r + 8);
        }
    }

    float biasA[2], biasB[2];
    #pragma unroll
    for (int nt = 0; nt < 2; nt++) {
        int vc = bj * 64 + wc * 16 + nt * 8 + 2 * r;
        biasA[nt] = g_bvc[vc];
        biasB[nt] = g_bvc[vc + 1];
    }

    // ldmatrix A base addresses (both buffers)
    const int matrow = (lane & 7) + ((lane >> 3) & 1) * 8;
    const int colh   = (lane >> 4) * 8;
    uint32_t habase[2], xabase[2];
    #pragma unroll
    for (int b = 0; b < 2; b++) {
        habase[b] = smem_u32(h_b[b]) + ((wm * 16 + matrow) * HSH + colh) * 2;
        xabase[b] = smem_u32(x_b[b]) + ((wm * 16 + matrow) * HSH + colh) * 2;
    }

    const int odd = lane & 1;
    const int lrow = rA + (odd ? 8 : 0);
    const int myrow = nBase + lrow;
    int lcol[2];
    #pragma unroll
    for (int nt = 0; nt < 2; nt++) lcol[nt] = wc * 4 + nt * 2 + (r >> 1);

    // h staging (per-warp rows): warp stages rows 4*warp..4*warp+3
    const int hrow = warp * 4 + (lane >> 3);
    const int hl8  = (lane & 7) * 4;   // 4 chunks of 16B per lane

    // x staging (block-cooperative): 4 x 16B per thread
    int xrow[4], xc8[4];
    #pragma unroll
    for (int i = 0; i < 4; i++) {
        int f = i * 256 + tid;
        xrow[i] = f >> 5; xc8[i] = (f & 31) << 3;
    }

    // h store: lanes with (r>>1)==0 store one row each (8B = 4 cols)
    const bool hstore = (r < 2);
    __half* hout0 = g_hh + (size_t)myrow * HH + j0 + wc * 4;

    float cst[2] = {0.f, 0.f};

    // prime: stage x(0) into x_b[0]
    #pragma unroll
    for (int i = 0; i < 4; i++) {
        const __half* src = g_xh + ((size_t)(nBase + xrow[i]) * TT) * 256 + xc8[i];
        uint4 v = __ldg((const uint4*)src);
        *(uint4*)(x_b[0] + xrow[i] * HSH + xc8[i]) = v;
    }
    __syncthreads();

    for (int t = 0; t < TT; t++) {
        const int cb = t & 1, nb = (t + 1) & 1;

        // prefetch x(t+1) regs
        uint4 xr[4];
        if (t + 1 < TT) {
            #pragma unroll
            for (int i = 0; i < 4; i++) {
                const __half* src = g_xh
                    + ((size_t)(nBase + xrow[i]) * TT + (t + 1)) * 256 + xc8[i];
                xr[i] = __ldg((const uint4*)src);
            }
        }

        // acc = bias; x-mma (split-K) — fills the wait window
        float acc[2][4], acb[2][4];
        #pragma unroll
        for (int nt = 0; nt < 2; nt++) {
            acc[nt][0] = biasA[nt]; acc[nt][1] = biasB[nt];
            acc[nt][2] = biasA[nt]; acc[nt][3] = biasB[nt];
            acb[nt][0] = 0.f; acb[nt][1] = 0.f; acb[nt][2] = 0.f; acb[nt][3] = 0.f;
        }
        #pragma unroll
        for (int kc = 0; kc < 8; kc++) {
            uint32_t a0, a1, a2, a3, c0, c1, c2, c3;
            ldsm4(a0, a1, a2, a3, xabase[cb] + kc * 32);
            ldsm4(c0, c1, c2, c3, xabase[cb] + (kc + 8) * 32);
            mma16(acc[0], a0, a1, a2, a3, xb0[kc][0], xb1[kc][0]);
            mma16(acc[1], a0, a1, a2, a3, xb0[kc][1], xb1[kc][1]);
            mma16(acb[0], c0, c1, c2, c3, xb0[kc + 8][0], xb1[kc + 8][0]);
            mma16(acb[1], c0, c1, c2, c3, xb0[kc + 8][1], xb1[kc + 8][1]);
        }

        // stage x(t+1)
        if (t + 1 < TT) {
            #pragma unroll
            for (int i = 0; i < 4; i++)
                *(uint4*)(x_b[nb] + xrow[i] * HSH + xc8[i]) = xr[i];
        }

        if (t > 0) {
            // per-warp poll, then per-warp h staging
            if (lane == 0) {
                unsigned target = 128u * (unsigned)t;
                while (ld_acq(bar) < target) { }
            }
            __syncwarp();
            const __half* hsrc = g_hh + cb * (NB * HH) + (nBase + hrow) * HH;
            #pragma unroll
            for (int i = 0; i < 4; i++) {
                uint4 v = __ldcg((const uint4*)(hsrc + (hl8 + i) * 8));
                *(uint4*)(h_b[cb] + hrow * HSH + (hl8 + i) * 8) = v;
            }
        }
        __syncthreads();   // the ONLY block barrier per step

        if (t > 0) {
            #pragma unroll
            for (int kc = 0; kc < 8; kc++) {
                uint32_t a0, a1, a2, a3, c0, c1, c2, c3;
                ldsm4(a0, a1, a2, a3, habase[cb] + kc * 32);
                ldsm4(c0, c1, c2, c3, habase[cb] + (kc + 8) * 32);
                mma16(acc[0], a0, a1, a2, a3, hb0[kc][0], hb1[kc][0]);
                mma16(acc[1], a0, a1, a2, a3, hb0[kc][1], hb1[kc][1]);
                mma16(acb[0], c0, c1, c2, c3, hb0[kc + 8][0], hb1[kc + 8][0]);
                mma16(acb[1], c0, c1, c2, c3, hb0[kc + 8][1], hb1[kc + 8][1]);
            }
        }
        #pragma unroll
        for (int nt = 0; nt < 2; nt++)
            #pragma unroll
            for (int j = 0; j < 4; j++) acc[nt][j] += acb[nt][j];

        // cell update (lane-pair gate exchange)
        float hv[2];
        #pragma unroll
        for (int nt = 0; nt < 2; nt++) {
            float s0 = odd ? acc[nt][0] : acc[nt][2];
            float s1 = odd ? acc[nt][1] : acc[nt][3];
            float r0 = __shfl_xor_sync(0xFFFFFFFFu, s0, 1);
            float r1 = __shfl_xor_sync(0xFFFFFFFFu, s1, 1);
            float iv, fv, gv, ov;
            if (odd) { iv = r0; fv = r1; gv = acc[nt][2]; ov = acc[nt][3]; }
            else     { iv = acc[nt][0]; fv = acc[nt][1]; gv = r0; ov = r1; }
            float ig = sigm(iv), fg = sigm(fv), gg = tanh_acc(gv), og = sigm(ov);
            float c = fg * cst[nt] + ig * gg;
            cst[nt] = c;
            hv[nt] = og * tanh_acc(c);
        }

        if (t < TT - 1) {
            // gather 4 cols into the r<2 lane of each pair: this lane has
            // cols {0,2}, partner (lane^2) has {1,3}
            float p0 = __shfl_xor_sync(0xFFFFFFFFu, hv[0], 2);
            float p1 = __shfl_xor_sync(0xFFFFFFFFu, hv[1], 2);
            if (hstore) {
                __half2 ha = __floats2half2_rn(hv[0], p0);   // cols 0,1
                __half2 hb = __floats2half2_rn(hv[1], p1);   // cols 2,3
                uint2 pk; pk.x = *(uint32_t*)&ha; pk.y = *(uint32_t*)&hb;
                __stcg((uint2*)(hout0 + nb * (NB * HH * 1)), pk);
            }
            __syncwarp();
            if (lane == 0) red_rel(bar, 1u);
        } else {
            out[myrow * HH + j0 + lcol[0]] = hv[0];
            out[myrow * HH + j0 + lcol[1]] = hv[1];
            if (out_n >= 2 * NB * HH) {
                out[NB * HH + myrow * HH + j0 + lcol[0]] = cst[0];
                out[NB * HH + myrow * HH + j0 + lcol[1]] = cst[1];
            }
        }
    }
}

// ================= launch ==================================================
extern "C" void kernel_launch(void* const* d_in, const int* in_sizes, int n_in,
                              void* d_out, int out_size) {
    const float* x    = (const float*)d_in[0];
    const float* w_ii = (const float*)d_in[1];
    const float* w_hi = (const float*)d_in[2];
    const float* w_if = (const float*)d_in[3];
    const float* w_hf = (const float*)d_in[4];
    const float* w_ig = (const float*)d_in[5];
    const float* w_hg = (const float*)d_in[6];
    const float* w_io = (const float*)d_in[7];
    const float* w_ho = (const float*)d_in[8];
    const float* b_ii = (const float*)d_in[9];
    const float* b_hi = (const float*)d_in[10];
    const float* b_if = (const float*)d_in[11];
    const float* b_hf = (const float*)d_in[12];
    const float* b_ig = (const float*)d_in[13];
    const float* b_hg = (const float*)d_in[14];
    const float* b_io = (const float*)d_in[15];
    const float* b_ho = (const float*)d_in[16];
    float* out = (float*)d_out;

    void* barAddr = nullptr;
    cudaGetSymbolAddress(&barAddr, g_bars);
    cudaMemsetAsync(barAddr, 0, 8 * 32 * sizeof(unsigned), 0);

    prep_w<<<2048, 256>>>(w_ii, w_if, w_ig, w_io, w_hi, w_hf, w_hg, w_ho);
    prep_b<<<4, 256>>>(b_ii, b_hi, b_if, b_hf, b_ig, b_hg, b_io, b_ho);
    prep_x<<<(NB * TT * 256 / 4) / 256, 256>>>(x);

    static int smem_set = 0;
    if (!smem_set) {
        cudaFuncSetAttribute(lstm_rec_kernel,
                             cudaFuncAttributeMaxDynamicSharedMemorySize, REC_SMEM);
        smem_set = 1;
    }
    lstm_rec_kernel<<<128, 256, REC_SMEM>>>(out, out_size);
}

// round 12
// speedup vs baseline: 1.1818x; 1.1818x over previous
#include <cuda_runtime.h>
#include <cuda_fp16.h>
#include <stdint.h>

#define TT 512
#define NB 256
#define HH 256
#define GG 1024

// vcol = jj*4 + gate  (jj = hidden col; gate: 0=i 1=f 2=g 3=o)
__device__ __half   g_xh[(size_t)NB * TT * 256];  // x in fp16 [n][t][d]
__device__ __half   g_hh[2 * NB * HH];            // fp16 hidden, double buffered
__device__ __half   g_wtx[1024 * 256];            // [vcol][k] Wx fp16
__device__ __half   g_wth[1024 * 256];            // [vcol][k] Wh fp16
__device__ float    g_bvc[1024];                  // combined bias per vcol
__device__ unsigned g_bars[8 * 32];

__device__ __forceinline__ void mma16(float d[4], uint32_t a0, uint32_t a1,
                                      uint32_t a2, uint32_t a3, uint32_t b0, uint32_t b1) {
    asm volatile("mma.sync.aligned.m16n8k16.row.col.f32.f16.f16.f32 "
                 "{%0,%1,%2,%3}, {%4,%5,%6,%7}, {%8,%9}, {%0,%1,%2,%3};\n"
                 : "+f"(d[0]), "+f"(d[1]), "+f"(d[2]), "+f"(d[3])
                 : "r"(a0), "r"(a1), "r"(a2), "r"(a3), "r"(b0), "r"(b1));
}
__device__ __forceinline__ float sigm(float x) { return __fdividef(1.f, 1.f + __expf(-x)); }
__device__ __forceinline__ float tanh_acc(float x) { return 1.f - __fdividef(2.f, __expf(2.f * x) + 1.f); }
__device__ __forceinline__ unsigned ld_acq(const unsigned* p) {
    unsigned v; asm volatile("ld.acquire.gpu.global.u32 %0, [%1];" : "=r"(v) : "l"(p)); return v;
}
__device__ __forceinline__ void red_rel(unsigned* p, unsigned v) {
    asm volatile("red.release.gpu.global.add.u32 [%0], %1;" :: "l"(p), "r"(v) : "memory");
}
__device__ __forceinline__ uint32_t smem_u32(const void* p) {
    return (uint32_t)__cvta_generic_to_shared(p);
}
__device__ __forceinline__ void ldsm4(uint32_t& a0, uint32_t& a1, uint32_t& a2,
                                      uint32_t& a3, uint32_t addr) {
    asm volatile("ldmatrix.sync.aligned.m8n8.x4.shared.b16 {%0,%1,%2,%3}, [%4];"
                 : "=r"(a0), "=r"(a1), "=r"(a2), "=r"(a3) : "r"(addr));
}

// ============ Prep kernels ================================================
__global__ void prep_w(const float* __restrict__ xi, const float* __restrict__ xf,
                       const float* __restrict__ xg, const float* __restrict__ xo,
                       const float* __restrict__ hi, const float* __restrict__ hf,
                       const float* __restrict__ hg, const float* __restrict__ ho) {
    int which = blockIdx.x >> 10, vv = blockIdx.x & 1023;
    int jj = vv >> 2, gt = vv & 3, k = threadIdx.x;
    const float* w;
    if (which == 0) w = (gt == 0) ? xi : (gt == 1) ? xf : (gt == 2) ? xg : xo;
    else            w = (gt == 0) ? hi : (gt == 1) ? hf : (gt == 2) ? hg : ho;
    __half* dst = which == 0 ? g_wtx : g_wth;
    dst[((size_t)vv << 8) + k] = __float2half_rn(w[k * 256 + jj]);
}
__global__ void prep_b(const float* __restrict__ b0, const float* __restrict__ b1,
                       const float* __restrict__ b2, const float* __restrict__ b3,
                       const float* __restrict__ b4, const float* __restrict__ b5,
                       const float* __restrict__ b6, const float* __restrict__ b7) {
    int vv = blockIdx.x * 256 + threadIdx.x;
    int jj = vv >> 2, gt = vv & 3;
    const float* bx = (gt == 0) ? b0 : (gt == 1) ? b2 : (gt == 2) ? b4 : b6;
    const float* bh = (gt == 0) ? b1 : (gt == 1) ? b3 : (gt == 2) ? b5 : b7;
    g_bvc[vv] = bx[jj] + bh[jj];
}
__global__ void prep_x(const float* __restrict__ x) {
    size_t i = ((size_t)blockIdx.x * 256 + threadIdx.x);
    float4 v = *(const float4*)(x + i * 4);
    __half2 h0 = __floats2half2_rn(v.x, v.y);
    __half2 h1 = __floats2half2_rn(v.z, v.w);
    uint2 pk; pk.x = *(uint32_t*)&h0; pk.y = *(uint32_t*)&h1;
    *(uint2*)(g_xh + i * 4) = pk;
}

// ================= Fused persistent LSTM ===================================
// 128 CTAs: bn=blk>>4, bj=blk&15. 8 warps: wm=warp&1, wc=warp>>1.
// Warp: 16 rows x 16 vcols. Wx+Wh fragments in registers.
// Per step (3 block barriers): poll(tid0) | sync | stage h + x(t+1) | sync |
// interleaved x-mma + h-mma (4 indep chains) | cell | shfl-gather STG |
// sync | release(tid0).
#define HSH 264
#define REC_SMEM (3 * 32 * HSH * 2)   // h_b (1) + x_b (2)

__global__ void __launch_bounds__(256, 1) lstm_rec_kernel(
    float* __restrict__ out, int out_n)
{
    extern __shared__ __align__(16) __half sm[];
    __half* h_b    = sm;
    __half* x_b[2] = { sm + 32 * HSH, sm + 2 * 32 * HSH };

    const int tid = threadIdx.x, lane = tid & 31, warp = tid >> 5;
    const int wm = warp & 1, wc = warp >> 1;
    const int bn = blockIdx.x >> 4, bj = blockIdx.x & 15;
    const int nBase = bn * 32, j0 = bj * 16;
    const int u = lane >> 2, r = lane & 3;
    const int rA = wm * 16 + u;

    unsigned* bar = &g_bars[bn * 32];

    // ---- persistent B fragments: Wh and Wx ----
    uint32_t hb0[16][2], hb1[16][2], xb0[16][2], xb1[16][2];
    #pragma unroll
    for (int nt = 0; nt < 2; nt++) {
        const size_t vrow = (size_t)(bj * 64 + wc * 16 + nt * 8 + u) * 256;
        const __half* wph = g_wth + vrow;
        const __half* wpx = g_wtx + vrow;
        #pragma unroll
        for (int kc = 0; kc < 16; kc++) {
            hb0[kc][nt] = *(const uint32_t*)(wph + kc * 16 + 2 * r);
            hb1[kc][nt] = *(const uint32_t*)(wph + kc * 16 + 2 * r + 8);
            xb0[kc][nt] = *(const uint32_t*)(wpx + kc * 16 + 2 * r);
            xb1[kc][nt] = *(const uint32_t*)(wpx + kc * 16 + 2 * r + 8);
        }
    }

    float biasA[2], biasB[2];
    #pragma unroll
    for (int nt = 0; nt < 2; nt++) {
        int vc = bj * 64 + wc * 16 + nt * 8 + 2 * r;
        biasA[nt] = g_bvc[vc];
        biasB[nt] = g_bvc[vc + 1];
    }

    // ldmatrix A base addresses
    const int matrow = (lane & 7) + ((lane >> 3) & 1) * 8;
    const int colh   = (lane >> 4) * 8;
    const uint32_t habase = smem_u32(h_b) + ((wm * 16 + matrow) * HSH + colh) * 2;
    uint32_t xabase[2];
    #pragma unroll
    for (int b = 0; b < 2; b++)
        xabase[b] = smem_u32(x_b[b]) + ((wm * 16 + matrow) * HSH + colh) * 2;

    const int odd = lane & 1;
    const int lrow = rA + (odd ? 8 : 0);
    const int myrow = nBase + lrow;
    int lcol[2];
    #pragma unroll
    for (int nt = 0; nt < 2; nt++) lcol[nt] = wc * 4 + nt * 2 + (r >> 1);

    // staging coords (4 x 16B per thread, block-cooperative)
    int xrow[4], xc8[4];
    #pragma unroll
    for (int i = 0; i < 4; i++) {
        int f = i * 256 + tid;
        xrow[i] = f >> 5; xc8[i] = (f & 31) << 3;
    }

    // direct h store: lanes r<2 each store one row (8B = 4 cols)
    const bool hstore = (r < 2);
    __half* hout0 = g_hh + (size_t)myrow * HH + j0 + wc * 4;

    float cst[2] = {0.f, 0.f};

    // prime: stage x(0) into x_b[0]
    #pragma unroll
    for (int i = 0; i < 4; i++) {
        const __half* src = g_xh + ((size_t)(nBase + xrow[i]) * TT) * 256 + xc8[i];
        uint4 v = __ldg((const uint4*)src);
        *(uint4*)(x_b[0] + xrow[i] * HSH + xc8[i]) = v;
    }
    __syncthreads();

    for (int t = 0; t < TT; t++) {
        const int cb = t & 1, nb = (t + 1) & 1;

        // prefetch x(t+1) regs (independent)
        uint4 xr[4];
        if (t + 1 < TT) {
            #pragma unroll
            for (int i = 0; i < 4; i++) {
                const __half* src = g_xh
                    + ((size_t)(nBase + xrow[i]) * TT + (t + 1)) * 256 + xc8[i];
                xr[i] = __ldg((const uint4*)src);
            }
        }

        if (t > 0 && tid == 0) {
            unsigned target = 16u * (unsigned)t;
            while (ld_acq(bar) < target) { }
        }
        __syncthreads();   // barrier observed by all; x_b[cb] reads of t-1 done

        // stage h(t) and x(t+1)
        if (t > 0) {
            const __half* hsrc = g_hh + cb * (NB * HH) + nBase * HH;
            #pragma unroll
            for (int i = 0; i < 4; i++)
                *(uint4*)(h_b + xrow[i] * HSH + xc8[i]) =
                    __ldcg((const uint4*)(hsrc + xrow[i] * HH + xc8[i]));
        }
        if (t + 1 < TT) {
            #pragma unroll
            for (int i = 0; i < 4; i++)
                *(uint4*)(x_b[nb] + xrow[i] * HSH + xc8[i]) = xr[i];
        }
        __syncthreads();

        // interleaved x-mma (acc, init bias) + h-mma (acb, init 0):
        // 4 independent chains, dependency latency mutually hidden
        float acc[2][4], acb[2][4];
        #pragma unroll
        for (int nt = 0; nt < 2; nt++) {
            acc[nt][0] = biasA[nt]; acc[nt][1] = biasB[nt];
            acc[nt][2] = biasA[nt]; acc[nt][3] = biasB[nt];
            acb[nt][0] = 0.f; acb[nt][1] = 0.f; acb[nt][2] = 0.f; acb[nt][3] = 0.f;
        }
        if (t > 0) {
            #pragma unroll
            for (int kc = 0; kc < 16; kc++) {
                uint32_t a0, a1, a2, a3, c0, c1, c2, c3;
                ldsm4(a0, a1, a2, a3, xabase[cb] + kc * 32);
                ldsm4(c0, c1, c2, c3, habase + kc * 32);
                mma16(acc[0], a0, a1, a2, a3, xb0[kc][0], xb1[kc][0]);
                mma16(acb[0], c0, c1, c2, c3, hb0[kc][0], hb1[kc][0]);
                mma16(acc[1], a0, a1, a2, a3, xb0[kc][1], xb1[kc][1]);
                mma16(acb[1], c0, c1, c2, c3, hb0[kc][1], hb1[kc][1]);
            }
        } else {
            #pragma unroll
            for (int kc = 0; kc < 16; kc++) {
                uint32_t a0, a1, a2, a3;
                ldsm4(a0, a1, a2, a3, xabase[cb] + kc * 32);
                mma16(acc[0], a0, a1, a2, a3, xb0[kc][0], xb1[kc][0]);
                mma16(acc[1], a0, a1, a2, a3, xb0[kc][1], xb1[kc][1]);
            }
        }
        #pragma unroll
        for (int nt = 0; nt < 2; nt++)
            #pragma unroll
            for (int j = 0; j < 4; j++) acc[nt][j] += acb[nt][j];

        // cell update (lane-pair gate exchange)
        float hv[2];
        #pragma unroll
        for (int nt = 0; nt < 2; nt++) {
            float s0 = odd ? acc[nt][0] : acc[nt][2];
            float s1 = odd ? acc[nt][1] : acc[nt][3];
            float r0 = __shfl_xor_sync(0xFFFFFFFFu, s0, 1);
            float r1 = __shfl_xor_sync(0xFFFFFFFFu, s1, 1);
            float iv, fv, gv, ov;
            if (odd) { iv = r0; fv = r1; gv = acc[nt][2]; ov = acc[nt][3]; }
            else     { iv = acc[nt][0]; fv = acc[nt][1]; gv = r0; ov = r1; }
            float ig = sigm(iv), fg = sigm(fv), gg = tanh_acc(gv), og = sigm(ov);
            float c = fg * cst[nt] + ig * gg;
            cst[nt] = c;
            hv[nt] = og * tanh_acc(c);
        }

        if (t < TT - 1) {
            // gather partner cols (lane^2) and store 4 cols (8B) per row
            float p0 = __shfl_xor_sync(0xFFFFFFFFu, hv[0], 2);
            float p1 = __shfl_xor_sync(0xFFFFFFFFu, hv[1], 2);
            if (hstore) {
                __half2 ha = __floats2half2_rn(hv[0], p0);   // cols 0,1
                __half2 hb = __floats2half2_rn(hv[1], p1);   // cols 2,3
                uint2 pk; pk.x = *(uint32_t*)&ha; pk.y = *(uint32_t*)&hb;
                __stcg((uint2*)(hout0 + nb * (NB * HH)), pk);
            }
            __syncthreads();   // all warps' STG before tid0's release
            if (tid == 0) red_rel(bar, 1u);
        } else {
            out[myrow * HH + j0 + lcol[0]] = hv[0];
            out[myrow * HH + j0 + lcol[1]] = hv[1];
            if (out_n >= 2 * NB * HH) {
                out[NB * HH + myrow * HH + j0 + lcol[0]] = cst[0];
                out[NB * HH + myrow * HH + j0 + lcol[1]] = cst[1];
            }
        }
    }
}

// ================= launch ==================================================
extern "C" void kernel_launch(void* const* d_in, const int* in_sizes, int n_in,
                              void* d_out, int out_size) {
    const float* x    = (const float*)d_in[0];
    const float* w_ii = (const float*)d_in[1];
    const float* w_hi = (const float*)d_in[2];
    const float* w_if = (const float*)d_in[3];
    const float* w_hf = (const float*)d_in[4];
    const float* w_ig = (const float*)d_in[5];
    const float* w_hg = (const float*)d_in[6];
    const float* w_io = (const float*)d_in[7];
    const float* w_ho = (const float*)d_in[8];
    const float* b_ii = (const float*)d_in[9];
    const float* b_hi = (const float*)d_in[10];
    const float* b_if = (const float*)d_in[11];
    const float* b_hf = (const float*)d_in[12];
    const float* b_ig = (const float*)d_in[13];
    const float* b_hg = (const float*)d_in[14];
    const float* b_io = (const float*)d_in[15];
    const float* b_ho = (const float*)d_in[16];
    float* out = (float*)d_out;

    void* barAddr = nullptr;
    cudaGetSymbolAddress(&barAddr, g_bars);
    cudaMemsetAsync(barAddr, 0, 8 * 32 * sizeof(unsigned), 0);

    prep_w<<<2048, 256>>>(w_ii, w_if, w_ig, w_io, w_hi, w_hf, w_hg, w_ho);
    prep_b<<<4, 256>>>(b_ii, b_hi, b_if, b_hf, b_ig, b_hg, b_io, b_ho);
    prep_x<<<(NB * TT * 256 / 4) / 256, 256>>>(x);

    static int smem_set = 0;
    if (!smem_set) {
        cudaFuncSetAttribute(lstm_rec_kernel,
                             cudaFuncAttributeMaxDynamicSharedMemorySize, REC_SMEM);
        smem_set = 1;
    }
    lstm_rec_kernel<<<128, 256, REC_SMEM>>>(out, out_size);
}

// round 13
// speedup vs baseline: 1.3333x; 1.1282x over previous
#include <cuda_runtime.h>
#include <cuda_fp16.h>
#include <stdint.h>

#define TT 512
#define NB 256
#define HH 256
#define GG 1024

// vcol = jj*4 + gate  (jj = hidden col; gate: 0=i 1=f 2=g 3=o)
__device__ __half   g_xh[(size_t)NB * TT * 256];  // x in fp16 [n][t][d]
__device__ __half   g_hh[2 * NB * HH];            // fp16 hidden, double buffered
__device__ __half   g_wtx[1024 * 256];            // [vcol][k] Wx fp16
__device__ __half   g_wth[1024 * 256];            // [vcol][k] Wh fp16
__device__ float    g_bvc[1024];                  // combined bias per vcol
__device__ unsigned g_bars[8 * 32];

__device__ __forceinline__ void mma16(float d[4], uint32_t a0, uint32_t a1,
                                      uint32_t a2, uint32_t a3, uint32_t b0, uint32_t b1) {
    asm volatile("mma.sync.aligned.m16n8k16.row.col.f32.f16.f16.f32 "
                 "{%0,%1,%2,%3}, {%4,%5,%6,%7}, {%8,%9}, {%0,%1,%2,%3};\n"
                 : "+f"(d[0]), "+f"(d[1]), "+f"(d[2]), "+f"(d[3])
                 : "r"(a0), "r"(a1), "r"(a2), "r"(a3), "r"(b0), "r"(b1));
}
__device__ __forceinline__ float sigm(float x) { return __fdividef(1.f, 1.f + __expf(-x)); }
__device__ __forceinline__ float tanh_acc(float x) { return 1.f - __fdividef(2.f, __expf(2.f * x) + 1.f); }
__device__ __forceinline__ unsigned ld_acq(const unsigned* p) {
    unsigned v; asm volatile("ld.acquire.gpu.global.u32 %0, [%1];" : "=r"(v) : "l"(p)); return v;
}
__device__ __forceinline__ void red_rel(unsigned* p, unsigned v) {
    asm volatile("red.release.gpu.global.add.u32 [%0], %1;" :: "l"(p), "r"(v) : "memory");
}
__device__ __forceinline__ uint32_t smem_u32(const void* p) {
    return (uint32_t)__cvta_generic_to_shared(p);
}
__device__ __forceinline__ void ldsm4(uint32_t& a0, uint32_t& a1, uint32_t& a2,
                                      uint32_t& a3, uint32_t addr) {
    asm volatile("ldmatrix.sync.aligned.m8n8.x4.shared.b16 {%0,%1,%2,%3}, [%4];"
                 : "=r"(a0), "=r"(a1), "=r"(a2), "=r"(a3) : "r"(addr));
}

// ============ Prep kernels ================================================
__global__ void prep_w(const float* __restrict__ xi, const float* __restrict__ xf,
                       const float* __restrict__ xg, const float* __restrict__ xo,
                       const float* __restrict__ hi, const float* __restrict__ hf,
                       const float* __restrict__ hg, const float* __restrict__ ho) {
    int which = blockIdx.x >> 10, vv = blockIdx.x & 1023;
    int jj = vv >> 2, gt = vv & 3, k = threadIdx.x;
    const float* w;
    if (which == 0) w = (gt == 0) ? xi : (gt == 1) ? xf : (gt == 2) ? xg : xo;
    else            w = (gt == 0) ? hi : (gt == 1) ? hf : (gt == 2) ? hg : ho;
    __half* dst = which == 0 ? g_wtx : g_wth;
    dst[((size_t)vv << 8) + k] = __float2half_rn(w[k * 256 + jj]);
}
__global__ void prep_b(const float* __restrict__ b0, const float* __restrict__ b1,
                       const float* __restrict__ b2, const float* __restrict__ b3,
                       const float* __restrict__ b4, const float* __restrict__ b5,
                       const float* __restrict__ b6, const float* __restrict__ b7) {
    int vv = blockIdx.x * 256 + threadIdx.x;
    int jj = vv >> 2, gt = vv & 3;
    const float* bx = (gt == 0) ? b0 : (gt == 1) ? b2 : (gt == 2) ? b4 : b6;
    const float* bh = (gt == 0) ? b1 : (gt == 1) ? b3 : (gt == 2) ? b5 : b7;
    g_bvc[vv] = bx[jj] + bh[jj];
}
__global__ void prep_x(const float* __restrict__ x) {
    size_t i = ((size_t)blockIdx.x * 256 + threadIdx.x);
    float4 v = *(const float4*)(x + i * 4);
    __half2 h0 = __floats2half2_rn(v.x, v.y);
    __half2 h1 = __floats2half2_rn(v.z, v.w);
    uint2 pk; pk.x = *(uint32_t*)&h0; pk.y = *(uint32_t*)&h1;
    *(uint2*)(g_xh + i * 4) = pk;
}

// ================= Fused persistent LSTM (R10 schedule + direct h store) ===
// 128 CTAs: bn=blk>>4, bj=blk&15. 8 warps: wm=warp&1, wc=warp>>1.
// Warp: 16 rows x 16 vcols. Wx+Wh fragments in registers.
// Per step: x-mma (PRE-barrier: fills the inter-CTA wait window) | tid0 poll |
// sync | stage h(t) + x(t+1) | sync | h-mma split-K | cell |
// shfl-gather direct STG | sync | tid0 release.  (3 syncthreads/step)
#define HSH 264

__global__ void __launch_bounds__(256, 1) lstm_rec_kernel(
    float* __restrict__ out, int out_n)
{
    __shared__ __align__(16) __half h_s[32 * HSH];
    __shared__ __align__(16) __half x_s[32 * HSH];

    const int tid = threadIdx.x, lane = tid & 31, warp = tid >> 5;
    const int wm = warp & 1, wc = warp >> 1;
    const int bn = blockIdx.x >> 4, bj = blockIdx.x & 15;
    const int nBase = bn * 32, j0 = bj * 16;
    const int u = lane >> 2, r = lane & 3;
    const int rA = wm * 16 + u;

    unsigned* bar = &g_bars[bn * 32];

    // ---- persistent B fragments: Wh and Wx (vcol-contiguous rows) ----
    uint32_t hb0[16][2], hb1[16][2], xb0[16][2], xb1[16][2];
    #pragma unroll
    for (int nt = 0; nt < 2; nt++) {
        const size_t vrow = (size_t)(bj * 64 + wc * 16 + nt * 8 + u) * 256;
        const __half* wph = g_wth + vrow;
        const __half* wpx = g_wtx + vrow;
        #pragma unroll
        for (int kc = 0; kc < 16; kc++) {
            hb0[kc][nt] = *(const uint32_t*)(wph + kc * 16 + 2 * r);
            hb1[kc][nt] = *(const uint32_t*)(wph + kc * 16 + 2 * r + 8);
            xb0[kc][nt] = *(const uint32_t*)(wpx + kc * 16 + 2 * r);
            xb1[kc][nt] = *(const uint32_t*)(wpx + kc * 16 + 2 * r + 8);
        }
    }

    // bias per accumulator column
    float biasA[2], biasB[2];
    #pragma unroll
    for (int nt = 0; nt < 2; nt++) {
        int vc = bj * 64 + wc * 16 + nt * 8 + 2 * r;
        biasA[nt] = g_bvc[vc];
        biasB[nt] = g_bvc[vc + 1];
    }

    // ldmatrix A base addresses
    const int matrow = (lane & 7) + ((lane >> 3) & 1) * 8;
    const int colh   = (lane >> 4) * 8;
    const uint32_t habase = smem_u32(h_s) + ((wm * 16 + matrow) * HSH + colh) * 2;
    const uint32_t xabase = smem_u32(x_s) + ((wm * 16 + matrow) * HSH + colh) * 2;

    const int odd = lane & 1;
    const int lrow = rA + (odd ? 8 : 0);
    const int myrow = nBase + lrow;
    int lcol[2];
    #pragma unroll
    for (int nt = 0; nt < 2; nt++) lcol[nt] = wc * 4 + nt * 2 + (r >> 1);

    // staging coords (4 x 16B per thread)
    int xrow[4], xc8[4];
    #pragma unroll
    for (int i = 0; i < 4; i++) {
        int f = i * 256 + tid;
        xrow[i] = f >> 5; xc8[i] = (f & 31) << 3;
    }

    // direct h store: lanes with r<2 each store one 8B row-strip (4 cols)
    const bool hstore = (r < 2);
    __half* hout0 = g_hh + (size_t)myrow * HH + j0 + wc * 4;

    float cst[2] = {0.f, 0.f};

    // prime: stage x(0)
    #pragma unroll
    for (int i = 0; i < 4; i++) {
        const __half* src = g_xh + ((size_t)(nBase + xrow[i]) * TT) * 256 + xc8[i];
        uint4 v = __ldg((const uint4*)src);
        *(uint4*)(x_s + xrow[i] * HSH + xc8[i]) = v;
    }
    __syncthreads();

    for (int t = 0; t < TT; t++) {
        const int cb = t & 1, nb = (t + 1) & 1;

        // prefetch x(t+1) into regs (independent of everything)
        uint4 xr[4];
        if (t + 1 < TT) {
            #pragma unroll
            for (int i = 0; i < 4; i++) {
                const __half* src = g_xh
                    + ((size_t)(nBase + xrow[i]) * TT + (t + 1)) * 256 + xc8[i];
                xr[i] = __ldg((const uint4*)src);
            }
        }

        // acc = bias; x-mma (split-K) BEFORE the barrier — fills wait window
        float acc[2][4], acb[2][4];
        #pragma unroll
        for (int nt = 0; nt < 2; nt++) {
            acc[nt][0] = biasA[nt]; acc[nt][1] = biasB[nt];
            acc[nt][2] = biasA[nt]; acc[nt][3] = biasB[nt];
            acb[nt][0] = 0.f; acb[nt][1] = 0.f; acb[nt][2] = 0.f; acb[nt][3] = 0.f;
        }
        #pragma unroll
        for (int kc = 0; kc < 8; kc++) {
            uint32_t a0, a1, a2, a3, c0, c1, c2, c3;
            ldsm4(a0, a1, a2, a3, xabase + kc * 32);
            ldsm4(c0, c1, c2, c3, xabase + (kc + 8) * 32);
            mma16(acc[0], a0, a1, a2, a3, xb0[kc][0], xb1[kc][0]);
            mma16(acc[1], a0, a1, a2, a3, xb0[kc][1], xb1[kc][1]);
            mma16(acb[0], c0, c1, c2, c3, xb0[kc + 8][0], xb1[kc + 8][0]);
            mma16(acb[1], c0, c1, c2, c3, xb0[kc + 8][1], xb1[kc + 8][1]);
        }

        if (t > 0) {
            if (tid == 0) {
                unsigned target = 16u * (unsigned)t;
                while (ld_acq(bar) < target) { }
            }
        }
        __syncthreads();   // all warps past x-mma (x_s free) + barrier observed

        // stage h(t) (if any) and x(t+1)
        if (t > 0) {
            const __half* hsrc = g_hh + cb * (NB * HH) + nBase * HH;
            #pragma unroll
            for (int i = 0; i < 4; i++)
                *(uint4*)(h_s + xrow[i] * HSH + xc8[i]) =
                    __ldcg((const uint4*)(hsrc + xrow[i] * HH + xc8[i]));
        }
        if (t + 1 < TT) {
            #pragma unroll
            for (int i = 0; i < 4; i++)
                *(uint4*)(x_s + xrow[i] * HSH + xc8[i]) = xr[i];
        }
        __syncthreads();

        if (t > 0) {
            #pragma unroll
            for (int kc = 0; kc < 8; kc++) {
                uint32_t a0, a1, a2, a3, c0, c1, c2, c3;
                ldsm4(a0, a1, a2, a3, habase + kc * 32);
                ldsm4(c0, c1, c2, c3, habase + (kc + 8) * 32);
                mma16(acc[0], a0, a1, a2, a3, hb0[kc][0], hb1[kc][0]);
                mma16(acc[1], a0, a1, a2, a3, hb0[kc][1], hb1[kc][1]);
                mma16(acb[0], c0, c1, c2, c3, hb0[kc + 8][0], hb1[kc + 8][0]);
                mma16(acb[1], c0, c1, c2, c3, hb0[kc + 8][1], hb1[kc + 8][1]);
            }
        }
        #pragma unroll
        for (int nt = 0; nt < 2; nt++)
            #pragma unroll
            for (int j = 0; j < 4; j++) acc[nt][j] += acb[nt][j];

        // cell update (lane-pair gate exchange)
        float hv[2];
        #pragma unroll
        for (int nt = 0; nt < 2; nt++) {
            float s0 = odd ? acc[nt][0] : acc[nt][2];
            float s1 = odd ? acc[nt][1] : acc[nt][3];
            float r0 = __shfl_xor_sync(0xFFFFFFFFu, s0, 1);
            float r1 = __shfl_xor_sync(0xFFFFFFFFu, s1, 1);
            float iv, fv, gv, ov;
            if (odd) { iv = r0; fv = r1; gv = acc[nt][2]; ov = acc[nt][3]; }
            else     { iv = acc[nt][0]; fv = acc[nt][1]; gv = r0; ov = r1; }
            float ig = sigm(iv), fg = sigm(fv), gg = tanh_acc(gv), og = sigm(ov);
            float c = fg * cst[nt] + ig * gg;
            cst[nt] = c;
            hv[nt] = og * tanh_acc(c);
        }

        if (t < TT - 1) {
            // direct store: partner (lane^2) holds cols {1,3}; this lane {0,2}
            float p0 = __shfl_xor_sync(0xFFFFFFFFu, hv[0], 2);
            float p1 = __shfl_xor_sync(0xFFFFFFFFu, hv[1], 2);
            if (hstore) {
                __half2 ha = __floats2half2_rn(hv[0], p0);   // cols 0,1
                __half2 hb = __floats2half2_rn(hv[1], p1);   // cols 2,3
                uint2 pk; pk.x = *(uint32_t*)&ha; pk.y = *(uint32_t*)&hb;
                __stcg((uint2*)(hout0 + nb * (NB * HH)), pk);
            }
            __syncthreads();   // all warps' STG complete before release
            if (tid == 0) red_rel(bar, 1u);
        } else {
            out[myrow * HH + j0 + lcol[0]] = hv[0];
            out[myrow * HH + j0 + lcol[1]] = hv[1];
            if (out_n >= 2 * NB * HH) {
                out[NB * HH + myrow * HH + j0 + lcol[0]] = cst[0];
                out[NB * HH + myrow * HH + j0 + lcol[1]] = cst[1];
            }
        }
    }
}

// ================= launch ==================================================
extern "C" void kernel_launch(void* const* d_in, const int* in_sizes, int n_in,
                              void* d_out, int out_size) {
    const float* x    = (const float*)d_in[0];
    const float* w_ii = (const float*)d_in[1];
    const float* w_hi = (const float*)d_in[2];
    const float* w_if = (const float*)d_in[3];
    const float* w_hf = (const float*)d_in[4];
    const float* w_ig = (const float*)d_in[5];
    const float* w_hg = (const float*)d_in[6];
    const float* w_io = (const float*)d_in[7];
    const float* w_ho = (const float*)d_in[8];
    const float* b_ii = (const float*)d_in[9];
    const float* b_hi = (const float*)d_in[10];
    const float* b_if = (const float*)d_in[11];
    const float* b_hf = (const float*)d_in[12];
    const float* b_ig = (const float*)d_in[13];
    const float* b_hg = (const float*)d_in[14];
    const float* b_io = (const float*)d_in[15];
    const float* b_ho = (const float*)d_in[16];
    float* out = (float*)d_out;

    void* barAddr = nullptr;
    cudaGetSymbolAddress(&barAddr, g_bars);
    cudaMemsetAsync(barAddr, 0, 8 * 32 * sizeof(unsigned), 0);

    prep_w<<<2048, 256>>>(w_ii, w_if, w_ig, w_io, w_hi, w_hf, w_hg, w_ho);
    prep_b<<<4, 256>>>(b_ii, b_hi, b_if, b_hf, b_ig, b_hg, b_io, b_ho);
    prep_x<<<(NB * TT * 256 / 4) / 256, 256>>>(x);

    lstm_rec_kernel<<<128, 256>>>(out, out_size);
}

// round 14
// speedup vs baseline: 1.3596x; 1.0197x over previous
#include <cuda_runtime.h>
#include <cuda_fp16.h>
#include <stdint.h>

#define TT 512
#define NB 256
#define HH 256
#define GG 1024

// vcol = jj*4 + gate  (jj = hidden col; gate: 0=i 1=f 2=g 3=o)
__device__ __half   g_xh[(size_t)NB * TT * 256];  // x in fp16 [n][t][d]
__device__ __half   g_hh[2 * NB * HH];            // fp16 hidden, double buffered
__device__ __half   g_wtx[1024 * 256];            // [vcol][k] Wx fp16
__device__ __half   g_wth[1024 * 256];            // [vcol][k] Wh fp16
__device__ float    g_bvc[1024];                  // combined bias per vcol
__device__ unsigned g_flags[8 * 32];              // [group][cta_j] step flags

__device__ __forceinline__ void mma16(float d[4], uint32_t a0, uint32_t a1,
                                      uint32_t a2, uint32_t a3, uint32_t b0, uint32_t b1) {
    asm volatile("mma.sync.aligned.m16n8k16.row.col.f32.f16.f16.f32 "
                 "{%0,%1,%2,%3}, {%4,%5,%6,%7}, {%8,%9}, {%0,%1,%2,%3};\n"
                 : "+f"(d[0]), "+f"(d[1]), "+f"(d[2]), "+f"(d[3])
                 : "r"(a0), "r"(a1), "r"(a2), "r"(a3), "r"(b0), "r"(b1));
}
__device__ __forceinline__ float sigm(float x) { return __fdividef(1.f, 1.f + __expf(-x)); }
__device__ __forceinline__ float tanh_acc(float x) { return 1.f - __fdividef(2.f, __expf(2.f * x) + 1.f); }
__device__ __forceinline__ unsigned ld_acq(const unsigned* p) {
    unsigned v; asm volatile("ld.acquire.gpu.global.u32 %0, [%1];" : "=r"(v) : "l"(p)); return v;
}
__device__ __forceinline__ void st_rel(unsigned* p, unsigned v) {
    asm volatile("st.release.gpu.global.u32 [%0], %1;" :: "l"(p), "r"(v) : "memory");
}
__device__ __forceinline__ uint32_t smem_u32(const void* p) {
    return (uint32_t)__cvta_generic_to_shared(p);
}
__device__ __forceinline__ void ldsm4(uint32_t& a0, uint32_t& a1, uint32_t& a2,
                                      uint32_t& a3, uint32_t addr) {
    asm volatile("ldmatrix.sync.aligned.m8n8.x4.shared.b16 {%0,%1,%2,%3}, [%4];"
                 : "=r"(a0), "=r"(a1), "=r"(a2), "=r"(a3) : "r"(addr));
}

// ============ Prep kernels ================================================
__global__ void prep_w(const float* __restrict__ xi, const float* __restrict__ xf,
                       const float* __restrict__ xg, const float* __restrict__ xo,
                       const float* __restrict__ hi, const float* __restrict__ hf,
                       const float* __restrict__ hg, const float* __restrict__ ho) {
    int which = blockIdx.x >> 10, vv = blockIdx.x & 1023;
    int jj = vv >> 2, gt = vv & 3, k = threadIdx.x;
    const float* w;
    if (which == 0) w = (gt == 0) ? xi : (gt == 1) ? xf : (gt == 2) ? xg : xo;
    else            w = (gt == 0) ? hi : (gt == 1) ? hf : (gt == 2) ? hg : ho;
    __half* dst = which == 0 ? g_wtx : g_wth;
    dst[((size_t)vv << 8) + k] = __float2half_rn(w[k * 256 + jj]);
}
__global__ void prep_b(const float* __restrict__ b0, const float* __restrict__ b1,
                       const float* __restrict__ b2, const float* __restrict__ b3,
                       const float* __restrict__ b4, const float* __restrict__ b5,
                       const float* __restrict__ b6, const float* __restrict__ b7) {
    int vv = blockIdx.x * 256 + threadIdx.x;
    int jj = vv >> 2, gt = vv & 3;
    const float* bx = (gt == 0) ? b0 : (gt == 1) ? b2 : (gt == 2) ? b4 : b6;
    const float* bh = (gt == 0) ? b1 : (gt == 1) ? b3 : (gt == 2) ? b5 : b7;
    g_bvc[vv] = bx[jj] + bh[jj];
}
__global__ void prep_x(const float* __restrict__ x) {
    size_t i = ((size_t)blockIdx.x * 256 + threadIdx.x);
    float4 v = *(const float4*)(x + i * 4);
    __half2 h0 = __floats2half2_rn(v.x, v.y);
    __half2 h1 = __floats2half2_rn(v.z, v.w);
    uint2 pk; pk.x = *(uint32_t*)&h0; pk.y = *(uint32_t*)&h1;
    *(uint2*)(g_xh + i * 4) = pk;
}

// ================= Fused persistent LSTM (R10 + parallel flag sync) ========
// 128 CTAs: bn=blk>>4, bj=blk&15. 8 warps: wm=warp&1, wc=warp>>1.
// Warp: 16 rows x 16 vcols. Wx+Wh fragments in registers.
// Per step: x-mma (pre-barrier, fills wait window) | warp0 parallel flag poll
// | sync | stage h(t)+x(t+1) | sync | h-mma split-K | cell | smem bounce |
// sync | tid<64 pack+STG | bar.sync(1,64) | tid0 flag release.
#define HSH 264

__global__ void __launch_bounds__(256, 1) lstm_rec_kernel(
    float* __restrict__ out, int out_n)
{
    __shared__ __align__(16) __half h_s[32 * HSH];
    __shared__ __align__(16) __half x_s[32 * HSH];
    __shared__ __align__(16) float  hx_s[32 * 16];

    const int tid = threadIdx.x, lane = tid & 31, warp = tid >> 5;
    const int wm = warp & 1, wc = warp >> 1;
    const int bn = blockIdx.x >> 4, bj = blockIdx.x & 15;
    const int nBase = bn * 32, j0 = bj * 16;
    const int u = lane >> 2, r = lane & 3;
    const int rA = wm * 16 + u;

    unsigned* flags = &g_flags[bn * 32];

    // ---- persistent B fragments: Wh and Wx ----
    uint32_t hb0[16][2], hb1[16][2], xb0[16][2], xb1[16][2];
    #pragma unroll
    for (int nt = 0; nt < 2; nt++) {
        const size_t vrow = (size_t)(bj * 64 + wc * 16 + nt * 8 + u) * 256;
        const __half* wph = g_wth + vrow;
        const __half* wpx = g_wtx + vrow;
        #pragma unroll
        for (int kc = 0; kc < 16; kc++) {
            hb0[kc][nt] = *(const uint32_t*)(wph + kc * 16 + 2 * r);
            hb1[kc][nt] = *(const uint32_t*)(wph + kc * 16 + 2 * r + 8);
            xb0[kc][nt] = *(const uint32_t*)(wpx + kc * 16 + 2 * r);
            xb1[kc][nt] = *(const uint32_t*)(wpx + kc * 16 + 2 * r + 8);
        }
    }

    float biasA[2], biasB[2];
    #pragma unroll
    for (int nt = 0; nt < 2; nt++) {
        int vc = bj * 64 + wc * 16 + nt * 8 + 2 * r;
        biasA[nt] = g_bvc[vc];
        biasB[nt] = g_bvc[vc + 1];
    }

    // ldmatrix A base addresses
    const int matrow = (lane & 7) + ((lane >> 3) & 1) * 8;
    const int colh   = (lane >> 4) * 8;
    const uint32_t habase = smem_u32(h_s) + ((wm * 16 + matrow) * HSH + colh) * 2;
    const uint32_t xabase = smem_u32(x_s) + ((wm * 16 + matrow) * HSH + colh) * 2;

    const int odd = lane & 1;
    const int lrow = rA + (odd ? 8 : 0);
    const int myrow = nBase + lrow;
    int lcol[2];
    #pragma unroll
    for (int nt = 0; nt < 2; nt++) lcol[nt] = wc * 4 + nt * 2 + (r >> 1);

    // staging coords (4 x 16B per thread)
    int xrow[4], xc8[4];
    #pragma unroll
    for (int i = 0; i < 4; i++) {
        int f = i * 256 + tid;
        xrow[i] = f >> 5; xc8[i] = (f & 31) << 3;
    }

    float cst[2] = {0.f, 0.f};

    // prime: stage x(0)
    #pragma unroll
    for (int i = 0; i < 4; i++) {
        const __half* src = g_xh + ((size_t)(nBase + xrow[i]) * TT) * 256 + xc8[i];
        uint4 v = __ldg((const uint4*)src);
        *(uint4*)(x_s + xrow[i] * HSH + xc8[i]) = v;
    }
    __syncthreads();

    for (int t = 0; t < TT; t++) {
        const int cb = t & 1, nb = (t + 1) & 1;

        // prefetch x(t+1) regs (independent)
        uint4 xr[4];
        if (t + 1 < TT) {
            #pragma unroll
            for (int i = 0; i < 4; i++) {
                const __half* src = g_xh
                    + ((size_t)(nBase + xrow[i]) * TT + (t + 1)) * 256 + xc8[i];
                xr[i] = __ldg((const uint4*)src);
            }
        }

        // acc = bias; x-mma (split-K) BEFORE barrier — fills the wait window
        float acc[2][4], acb[2][4];
        #pragma unroll
        for (int nt = 0; nt < 2; nt++) {
            acc[nt][0] = biasA[nt]; acc[nt][1] = biasB[nt];
            acc[nt][2] = biasA[nt]; acc[nt][3] = biasB[nt];
            acb[nt][0] = 0.f; acb[nt][1] = 0.f; acb[nt][2] = 0.f; acb[nt][3] = 0.f;
        }
        #pragma unroll
        for (int kc = 0; kc < 8; kc++) {
            uint32_t a0, a1, a2, a3, c0, c1, c2, c3;
            ldsm4(a0, a1, a2, a3, xabase + kc * 32);
            ldsm4(c0, c1, c2, c3, xabase + (kc + 8) * 32);
            mma16(acc[0], a0, a1, a2, a3, xb0[kc][0], xb1[kc][0]);
            mma16(acc[1], a0, a1, a2, a3, xb0[kc][1], xb1[kc][1]);
            mma16(acb[0], c0, c1, c2, c3, xb0[kc + 8][0], xb1[kc + 8][0]);
            mma16(acb[1], c0, c1, c2, c3, xb0[kc + 8][1], xb1[kc + 8][1]);
        }

        if (t > 0) {
            // parallel flag poll: warp 0, lanes 0..15 each watch one CTA flag
            if (warp == 0) {
                bool done = (lane >= 16);
                const unsigned targ = (unsigned)t;
                while (!__all_sync(0xFFFFFFFFu, done)) {
                    if (!done) done = (ld_acq(&flags[lane]) >= targ);
                }
            }
        }
        __syncthreads();   // all warps past x-mma (x_s free) + flags observed

        // stage h(t) (if any) and x(t+1)
        if (t > 0) {
            const __half* hsrc = g_hh + cb * (NB * HH) + nBase * HH;
            #pragma unroll
            for (int i = 0; i < 4; i++)
                *(uint4*)(h_s + xrow[i] * HSH + xc8[i]) =
                    __ldcg((const uint4*)(hsrc + xrow[i] * HH + xc8[i]));
        }
        if (t + 1 < TT) {
            #pragma unroll
            for (int i = 0; i < 4; i++)
                *(uint4*)(x_s + xrow[i] * HSH + xc8[i]) = xr[i];
        }
        __syncthreads();

        if (t > 0) {
            #pragma unroll
            for (int kc = 0; kc < 8; kc++) {
                uint32_t a0, a1, a2, a3, c0, c1, c2, c3;
                ldsm4(a0, a1, a2, a3, habase + kc * 32);
                ldsm4(c0, c1, c2, c3, habase + (kc + 8) * 32);
                mma16(acc[0], a0, a1, a2, a3, hb0[kc][0], hb1[kc][0]);
                mma16(acc[1], a0, a1, a2, a3, hb0[kc][1], hb1[kc][1]);
                mma16(acb[0], c0, c1, c2, c3, hb0[kc + 8][0], hb1[kc + 8][0]);
                mma16(acb[1], c0, c1, c2, c3, hb0[kc + 8][1], hb1[kc + 8][1]);
            }
        }
        #pragma unroll
        for (int nt = 0; nt < 2; nt++)
            #pragma unroll
            for (int j = 0; j < 4; j++) acc[nt][j] += acb[nt][j];

        // cell update (lane-pair gate exchange)
        float hv[2];
        #pragma unroll
        for (int nt = 0; nt < 2; nt++) {
            float s0 = odd ? acc[nt][0] : acc[nt][2];
            float s1 = odd ? acc[nt][1] : acc[nt][3];
            float r0 = __shfl_xor_sync(0xFFFFFFFFu, s0, 1);
            float r1 = __shfl_xor_sync(0xFFFFFFFFu, s1, 1);
            float iv, fv, gv, ov;
            if (odd) { iv = r0; fv = r1; gv = acc[nt][2]; ov = acc[nt][3]; }
            else     { iv = acc[nt][0]; fv = acc[nt][1]; gv = r0; ov = r1; }
            float ig = sigm(iv), fg = sigm(fv), gg = tanh_acc(gv), og = sigm(ov);
            float c = fg * cst[nt] + ig * gg;
            cst[nt] = c;
            hv[nt] = og * tanh_acc(c);
        }

        if (t < TT - 1) {
            // coalesced h store via smem bounce (R10 epilogue — proven fast)
            hx_s[lrow * 16 + lcol[0]] = hv[0];
            hx_s[lrow * 16 + lcol[1]] = hv[1];
            __syncthreads();
            if (tid < 64) {
                int row = tid >> 1, part = tid & 1;
                const float* s = hx_s + row * 16 + part * 8;
                __half2 h0 = __floats2half2_rn(s[0], s[1]);
                __half2 h1 = __floats2half2_rn(s[2], s[3]);
                __half2 h2 = __floats2half2_rn(s[4], s[5]);
                __half2 h3 = __floats2half2_rn(s[6], s[7]);
                uint4 pk;
                pk.x = *(uint32_t*)&h0; pk.y = *(uint32_t*)&h1;
                pk.z = *(uint32_t*)&h2; pk.w = *(uint32_t*)&h3;
                __half* hdst = g_hh + nb * (NB * HH)
                             + (nBase + row) * HH + j0 + part * 8;
                __stcg((uint4*)hdst, pk);
                // only the 64 storing threads need to order before release
                asm volatile("bar.sync 1, 64;" ::: "memory");
                if (tid == 0) st_rel(&flags[bj], (unsigned)(t + 1));
            }
            // warps 2-7 run ahead; hx_s rewrite is gated by step t+1's
            // block-wide syncs which warps 0-1 also participate in.
        } else {
            out[myrow * HH + j0 + lcol[0]] = hv[0];
            out[myrow * HH + j0 + lcol[1]] = hv[1];
            if (out_n >= 2 * NB * HH) {
                out[NB * HH + myrow * HH + j0 + lcol[0]] = cst[0];
                out[NB * HH + myrow * HH + j0 + lcol[1]] = cst[1];
            }
        }
    }
}

// ================= launch ==================================================
extern "C" void kernel_launch(void* const* d_in, const int* in_sizes, int n_in,
                              void* d_out, int out_size) {
    const float* x    = (const float*)d_in[0];
    const float* w_ii = (const float*)d_in[1];
    const float* w_hi = (const float*)d_in[2];
    const float* w_if = (const float*)d_in[3];
    const float* w_hf = (const float*)d_in[4];
    const float* w_ig = (const float*)d_in[5];
    const float* w_hg = (const float*)d_in[6];
    const float* w_io = (const float*)d_in[7];
    const float* w_ho = (const float*)d_in[8];
    const float* b_ii = (const float*)d_in[9];
    const float* b_hi = (const float*)d_in[10];
    const float* b_if = (const float*)d_in[11];
    const float* b_hf = (const float*)d_in[12];
    const float* b_ig = (const float*)d_in[13];
    const float* b_hg = (const float*)d_in[14];
    const float* b_io = (const float*)d_in[15];
    const float* b_ho = (const float*)d_in[16];
    float* out = (float*)d_out;

    void* flagAddr = nullptr;
    cudaGetSymbolAddress(&flagAddr, g_flags);
    cudaMemsetAsync(flagAddr, 0, 8 * 32 * sizeof(unsigned), 0);

    prep_w<<<2048, 256>>>(w_ii, w_if, w_ig, w_io, w_hi, w_hf, w_hg, w_ho);
    prep_b<<<4, 256>>>(b_ii, b_hi, b_if, b_hf, b_ig, b_hg, b_io, b_ho);
    prep_x<<<(NB * TT * 256 / 4) / 256, 256>>>(x);

    lstm_rec_kernel<<<128, 256>>>(out, out_size);
}

// round 15
// speedup vs baseline: 1.4378x; 1.0575x over previous
#include <cuda_runtime.h>
#include <cuda_fp16.h>
#include <stdint.h>

#define TT 512
#define NB 256
#define HH 256
#define GG 1024

// vcol = jj*4 + gate  (jj = hidden col; gate: 0=i 1=f 2=g 3=o)
__device__ __half   g_xh[(size_t)NB * TT * 256];  // x in fp16 [n][t][d]
__device__ __half   g_hh[2 * NB * HH];            // fp16 hidden, double buffered
__device__ __half   g_wtx[1024 * 256];            // [vcol][k] Wx fp16
__device__ __half   g_wth[1024 * 256];            // [vcol][k] Wh fp16
__device__ float    g_bvc[1024];                  // combined bias per vcol
__device__ unsigned g_bars[16 * 32];              // one counter per batch-group

__device__ __forceinline__ void mma16(float d[4], uint32_t a0, uint32_t a1,
                                      uint32_t a2, uint32_t a3, uint32_t b0, uint32_t b1) {
    asm volatile("mma.sync.aligned.m16n8k16.row.col.f32.f16.f16.f32 "
                 "{%0,%1,%2,%3}, {%4,%5,%6,%7}, {%8,%9}, {%0,%1,%2,%3};\n"
                 : "+f"(d[0]), "+f"(d[1]), "+f"(d[2]), "+f"(d[3])
                 : "r"(a0), "r"(a1), "r"(a2), "r"(a3), "r"(b0), "r"(b1));
}
__device__ __forceinline__ float sigm(float x) { return __fdividef(1.f, 1.f + __expf(-x)); }
__device__ __forceinline__ float tanh_acc(float x) { return 1.f - __fdividef(2.f, __expf(2.f * x) + 1.f); }
__device__ __forceinline__ unsigned ld_acq(const unsigned* p) {
    unsigned v; asm volatile("ld.acquire.gpu.global.u32 %0, [%1];" : "=r"(v) : "l"(p)); return v;
}
__device__ __forceinline__ void red_rel(unsigned* p, unsigned v) {
    asm volatile("red.release.gpu.global.add.u32 [%0], %1;" :: "l"(p), "r"(v) : "memory");
}
__device__ __forceinline__ uint32_t smem_u32(const void* p) {
    return (uint32_t)__cvta_generic_to_shared(p);
}
__device__ __forceinline__ void ldsm4(uint32_t& a0, uint32_t& a1, uint32_t& a2,
                                      uint32_t& a3, uint32_t addr) {
    asm volatile("ldmatrix.sync.aligned.m8n8.x4.shared.b16 {%0,%1,%2,%3}, [%4];"
                 : "=r"(a0), "=r"(a1), "=r"(a2), "=r"(a3) : "r"(addr));
}

// ============ Prep kernels ================================================
__global__ void prep_w(const float* __restrict__ xi, const float* __restrict__ xf,
                       const float* __restrict__ xg, const float* __restrict__ xo,
                       const float* __restrict__ hi, const float* __restrict__ hf,
                       const float* __restrict__ hg, const float* __restrict__ ho) {
    int which = blockIdx.x >> 10, vv = blockIdx.x & 1023;
    int jj = vv >> 2, gt = vv & 3, k = threadIdx.x;
    const float* w;
    if (which == 0) w = (gt == 0) ? xi : (gt == 1) ? xf : (gt == 2) ? xg : xo;
    else            w = (gt == 0) ? hi : (gt == 1) ? hf : (gt == 2) ? hg : ho;
    __half* dst = which == 0 ? g_wtx : g_wth;
    dst[((size_t)vv << 8) + k] = __float2half_rn(w[k * 256 + jj]);
}
__global__ void prep_b(const float* __restrict__ b0, const float* __restrict__ b1,
                       const float* __restrict__ b2, const float* __restrict__ b3,
                       const float* __restrict__ b4, const float* __restrict__ b5,
                       const float* __restrict__ b6, const float* __restrict__ b7) {
    int vv = blockIdx.x * 256 + threadIdx.x;
    int jj = vv >> 2, gt = vv & 3;
    const float* bx = (gt == 0) ? b0 : (gt == 1) ? b2 : (gt == 2) ? b4 : b6;
    const float* bh = (gt == 0) ? b1 : (gt == 1) ? b3 : (gt == 2) ? b5 : b7;
    g_bvc[vv] = bx[jj] + bh[jj];
}
__global__ void prep_x(const float* __restrict__ x) {
    size_t i = ((size_t)blockIdx.x * 256 + threadIdx.x);
    float4 v = *(const float4*)(x + i * 4);
    __half2 h0 = __floats2half2_rn(v.x, v.y);
    __half2 h1 = __floats2half2_rn(v.z, v.w);
    uint2 pk; pk.x = *(uint32_t*)&h0; pk.y = *(uint32_t*)&h1;
    *(uint2*)(g_xh + i * 4) = pk;
}

// ================= Fused persistent LSTM (R10 schedule, 8-CTA groups) ======
// 128 CTAs: bn=blk>>3 (16-row batch group, 16 groups), bj=blk&7 (128 vcols).
// 8 warps: warp wc owns 16 rows x 16 vcols (vcols bj*128 + wc*16 + [0,16)).
// Per step: x-mma (pre-barrier) | tid0 poll (8 arrivals) | sync |
// stage h(t)+x(t+1) (2 uint4/thread each) | sync | h-mma split-K | cell |
// smem bounce | sync | tid<64 pack+STG | tid0 release.
#define HSH 264

__global__ void __launch_bounds__(256, 1) lstm_rec_kernel(
    float* __restrict__ out, int out_n)
{
    __shared__ __align__(16) __half h_s[16 * HSH];
    __shared__ __align__(16) __half x_s[16 * HSH];
    __shared__ __align__(16) float  hx_s[16 * 32];

    const int tid = threadIdx.x, lane = tid & 31, warp = tid >> 5;
    const int bn = blockIdx.x >> 3, bj = blockIdx.x & 7;
    const int nBase = bn * 16, j0 = bj * 32;
    const int u = lane >> 2, r = lane & 3;

    unsigned* bar = &g_bars[bn * 32];

    // ---- persistent B fragments: Wh and Wx (vcol-contiguous rows) ----
    uint32_t hb0[16][2], hb1[16][2], xb0[16][2], xb1[16][2];
    #pragma unroll
    for (int nt = 0; nt < 2; nt++) {
        const size_t vrow = (size_t)(bj * 128 + warp * 16 + nt * 8 + u) * 256;
        const __half* wph = g_wth + vrow;
        const __half* wpx = g_wtx + vrow;
        #pragma unroll
        for (int kc = 0; kc < 16; kc++) {
            hb0[kc][nt] = *(const uint32_t*)(wph + kc * 16 + 2 * r);
            hb1[kc][nt] = *(const uint32_t*)(wph + kc * 16 + 2 * r + 8);
            xb0[kc][nt] = *(const uint32_t*)(wpx + kc * 16 + 2 * r);
            xb1[kc][nt] = *(const uint32_t*)(wpx + kc * 16 + 2 * r + 8);
        }
    }

    // bias per accumulator column
    float biasA[2], biasB[2];
    #pragma unroll
    for (int nt = 0; nt < 2; nt++) {
        int vc = bj * 128 + warp * 16 + nt * 8 + 2 * r;
        biasA[nt] = g_bvc[vc];
        biasB[nt] = g_bvc[vc + 1];
    }

    // ldmatrix A base addresses (16 rows)
    const int matrow = (lane & 7) + ((lane >> 3) & 1) * 8;
    const int colh   = (lane >> 4) * 8;
    const uint32_t habase = smem_u32(h_s) + (matrow * HSH + colh) * 2;
    const uint32_t xabase = smem_u32(x_s) + (matrow * HSH + colh) * 2;

    const int odd = lane & 1;
    const int lrow = u + (odd ? 8 : 0);            // 0..15
    const int myrow = nBase + lrow;
    int lcol[2];
    #pragma unroll
    for (int nt = 0; nt < 2; nt++) lcol[nt] = warp * 4 + nt * 2 + (r >> 1);

    // staging coords (2 x 16B per thread): 16 rows x 256 halves = 512 chunks
    int xrow[2], xc8[2];
    #pragma unroll
    for (int i = 0; i < 2; i++) {
        int f = i * 256 + tid;
        xrow[i] = f >> 5; xc8[i] = (f & 31) << 3;
    }

    float cst[2] = {0.f, 0.f};

    // prime: stage x(0)
    #pragma unroll
    for (int i = 0; i < 2; i++) {
        const __half* src = g_xh + ((size_t)(nBase + xrow[i]) * TT) * 256 + xc8[i];
        uint4 v = __ldg((const uint4*)src);
        *(uint4*)(x_s + xrow[i] * HSH + xc8[i]) = v;
    }
    __syncthreads();

    for (int t = 0; t < TT; t++) {
        const int cb = t & 1, nb = (t + 1) & 1;

        // prefetch x(t+1) into regs (independent)
        uint4 xr[2];
        if (t + 1 < TT) {
            #pragma unroll
            for (int i = 0; i < 2; i++) {
                const __half* src = g_xh
                    + ((size_t)(nBase + xrow[i]) * TT + (t + 1)) * 256 + xc8[i];
                xr[i] = __ldg((const uint4*)src);
            }
        }

        // acc = bias; x-mma (split-K) BEFORE barrier — fills the wait window
        float acc[2][4], acb[2][4];
        #pragma unroll
        for (int nt = 0; nt < 2; nt++) {
            acc[nt][0] = biasA[nt]; acc[nt][1] = biasB[nt];
            acc[nt][2] = biasA[nt]; acc[nt][3] = biasB[nt];
            acb[nt][0] = 0.f; acb[nt][1] = 0.f; acb[nt][2] = 0.f; acb[nt][3] = 0.f;
        }
        #pragma unroll
        for (int kc = 0; kc < 8; kc++) {
            uint32_t a0, a1, a2, a3, c0, c1, c2, c3;
            ldsm4(a0, a1, a2, a3, xabase + kc * 32);
            ldsm4(c0, c1, c2, c3, xabase + (kc + 8) * 32);
            mma16(acc[0], a0, a1, a2, a3, xb0[kc][0], xb1[kc][0]);
            mma16(acc[1], a0, a1, a2, a3, xb0[kc][1], xb1[kc][1]);
            mma16(acb[0], c0, c1, c2, c3, xb0[kc + 8][0], xb1[kc + 8][0]);
            mma16(acb[1], c0, c1, c2, c3, xb0[kc + 8][1], xb1[kc + 8][1]);
        }

        if (t > 0) {
            if (tid == 0) {
                unsigned target = 8u * (unsigned)t;
                while (ld_acq(bar) < target) { }
            }
        }
        __syncthreads();   // all warps past x-mma (x_s free) + barrier observed

        // stage h(t) (if any) and x(t+1)
        if (t > 0) {
            const __half* hsrc = g_hh + cb * (NB * HH) + nBase * HH;
            #pragma unroll
            for (int i = 0; i < 2; i++)
                *(uint4*)(h_s + xrow[i] * HSH + xc8[i]) =
                    __ldcg((const uint4*)(hsrc + xrow[i] * HH + xc8[i]));
        }
        if (t + 1 < TT) {
            #pragma unroll
            for (int i = 0; i < 2; i++)
                *(uint4*)(x_s + xrow[i] * HSH + xc8[i]) = xr[i];
        }
        __syncthreads();

        if (t > 0) {
            #pragma unroll
            for (int kc = 0; kc < 8; kc++) {
                uint32_t a0, a1, a2, a3, c0, c1, c2, c3;
                ldsm4(a0, a1, a2, a3, habase + kc * 32);
                ldsm4(c0, c1, c2, c3, habase + (kc + 8) * 32);
                mma16(acc[0], a0, a1, a2, a3, hb0[kc][0], hb1[kc][0]);
                mma16(acc[1], a0, a1, a2, a3, hb0[kc][1], hb1[kc][1]);
                mma16(acb[0], c0, c1, c2, c3, hb0[kc + 8][0], hb1[kc + 8][0]);
                mma16(acb[1], c0, c1, c2, c3, hb0[kc + 8][1], hb1[kc + 8][1]);
            }
        }
        #pragma unroll
        for (int nt = 0; nt < 2; nt++)
            #pragma unroll
            for (int j = 0; j < 4; j++) acc[nt][j] += acb[nt][j];

        // cell update (lane-pair gate exchange)
        float hv[2];
        #pragma unroll
        for (int nt = 0; nt < 2; nt++) {
            float s0 = odd ? acc[nt][0] : acc[nt][2];
            float s1 = odd ? acc[nt][1] : acc[nt][3];
            float r0 = __shfl_xor_sync(0xFFFFFFFFu, s0, 1);
            float r1 = __shfl_xor_sync(0xFFFFFFFFu, s1, 1);
            float iv, fv, gv, ov;
            if (odd) { iv = r0; fv = r1; gv = acc[nt][2]; ov = acc[nt][3]; }
            else     { iv = acc[nt][0]; fv = acc[nt][1]; gv = r0; ov = r1; }
            float ig = sigm(iv), fg = sigm(fv), gg = tanh_acc(gv), og = sigm(ov);
            float c = fg * cst[nt] + ig * gg;
            cst[nt] = c;
            hv[nt] = og * tanh_acc(c);
        }

        if (t < TT - 1) {
            // coalesced h store via smem bounce (proven epilogue)
            hx_s[lrow * 32 + lcol[0]] = hv[0];
            hx_s[lrow * 32 + lcol[1]] = hv[1];
            __syncthreads();
            if (tid < 64) {
                int row = tid >> 2, part = tid & 3;
                const float* s = hx_s + row * 32 + part * 8;
                __half2 h0 = __floats2half2_rn(s[0], s[1]);
                __half2 h1 = __floats2half2_rn(s[2], s[3]);
                __half2 h2 = __floats2half2_rn(s[4], s[5]);
                __half2 h3 = __floats2half2_rn(s[6], s[7]);
                uint4 pk;
                pk.x = *(uint32_t*)&h0; pk.y = *(uint32_t*)&h1;
                pk.z = *(uint32_t*)&h2; pk.w = *(uint32_t*)&h3;
                __half* hdst = g_hh + nb * (NB * HH)
                             + (nBase + row) * HH + j0 + part * 8;
                __stcg((uint4*)hdst, pk);
            }
            __syncthreads();
            if (tid == 0) red_rel(bar, 1u);
        } else {
            out[myrow * HH + j0 + lcol[0]] = hv[0];
            out[myrow * HH + j0 + lcol[1]] = hv[1];
            if (out_n >= 2 * NB * HH) {
                out[NB * HH + myrow * HH + j0 + lcol[0]] = cst[0];
                out[NB * HH + myrow * HH + j0 + lcol[1]] = cst[1];
            }
        }
    }
}

// ================= launch ==================================================
extern "C" void kernel_launch(void* const* d_in, const int* in_sizes, int n_in,
                              void* d_out, int out_size) {
    const float* x    = (const float*)d_in[0];
    const float* w_ii = (const float*)d_in[1];
    const float* w_hi = (const float*)d_in[2];
    const float* w_if = (const float*)d_in[3];
    const float* w_hf = (const float*)d_in[4];
    const float* w_ig = (const float*)d_in[5];
    const float* w_hg = (const float*)d_in[6];
    const float* w_io = (const float*)d_in[7];
    const float* w_ho = (const float*)d_in[8];
    const float* b_ii = (const float*)d_in[9];
    const float* b_hi = (const float*)d_in[10];
    const float* b_if = (const float*)d_in[11];
    const float* b_hf = (const float*)d_in[12];
    const float* b_ig = (const float*)d_in[13];
    const float* b_hg = (const float*)d_in[14];
    const float* b_io = (const float*)d_in[15];
    const float* b_ho = (const float*)d_in[16];
    float* out = (float*)d_out;

    void* barAddr = nullptr;
    cudaGetSymbolAddress(&barAddr, g_bars);
    cudaMemsetAsync(barAddr, 0, 16 * 32 * sizeof(unsigned), 0);

    prep_w<<<2048, 256>>>(w_ii, w_if, w_ig, w_io, w_hi, w_hf, w_hg, w_ho);
    prep_b<<<4, 256>>>(b_ii, b_hi, b_if, b_hf, b_ig, b_hg, b_io, b_ho);
    prep_x<<<(NB * TT * 256 / 4) / 256, 256>>>(x);

    lstm_rec_kernel<<<128, 256>>>(out, out_size);
}